// round 15
// baseline (speedup 1.0000x reference)
#include <cuda_runtime.h>
#include <cuda_bf16.h>
#include <stdint.h>
#include <math.h>

// Problem-shape capacities (this problem: N=16384, E=524288, IN=256, NH=64)
#define MAXN 16384
#define MAXE 524288
#define NHID 64

// ---- scratch (static __device__ arrays; no allocation allowed) ----
__device__ float g_h[(size_t)MAXN * NHID];   // projected features, 4 MB
__device__ int   g_outdeg[MAXN];
__device__ int   g_indeg[MAXN];
__device__ int   g_cursor[MAXN];
__device__ int   g_rowstart[MAXN + 1];
__device__ int   g_esrc[MAXE];
__device__ float g_ealpha[MAXE];
__device__ __nv_bfloat16 g_hi[(size_t)MAXN * NHID];  // rst split high, 2 MB
__device__ __nv_bfloat16 g_lo[(size_t)MAXN * NHID];  // rst split low,  2 MB

// ---------------------------------------------------------------------------
__device__ __forceinline__ uint32_t smem_u32(const void* p) {
    uint32_t a;
    asm("{ .reg .u64 t; cvta.to.shared.u64 t, %1; cvt.u32.u64 %0, t; }"
        : "=r"(a) : "l"(p));
    return a;
}
// SW128 swizzle on byte offsets (XOR bits[6:4] with bits[9:7])
#define SW128(o) ((o) ^ (((o) >> 3) & 0x70u))

__device__ __forceinline__ void ldm_x4(uint32_t& r0, uint32_t& r1,
                                       uint32_t& r2, uint32_t& r3, uint32_t addr) {
    asm volatile("ldmatrix.sync.aligned.m8n8.x4.shared.b16 {%0,%1,%2,%3}, [%4];"
                 : "=r"(r0), "=r"(r1), "=r"(r2), "=r"(r3) : "r"(addr));
}
__device__ __forceinline__ void mma_16816(float* c, const uint32_t* a, const uint32_t* b) {
    asm volatile(
        "mma.sync.aligned.m16n8k16.row.col.f32.bf16.bf16.f32 "
        "{%0,%1,%2,%3}, {%4,%5,%6,%7}, {%8,%9}, {%0,%1,%2,%3};"
        : "+f"(c[0]), "+f"(c[1]), "+f"(c[2]), "+f"(c[3])
        : "r"(a[0]), "r"(a[1]), "r"(a[2]), "r"(a[3]), "r"(b[0]), "r"(b[1]));
}

// ---------------------------------------------------------------------------
// 1) zero counters
__global__ void k_zero(int n) {
    int i = blockIdx.x * blockDim.x + threadIdx.x;
    if (i < n) { g_outdeg[i] = 0; g_indeg[i] = 0; g_cursor[i] = 0; }
}

// 2) degree histograms
__global__ void k_degrees(const int* __restrict__ src, const int* __restrict__ dst, int E) {
    int e = blockIdx.x * blockDim.x + threadIdx.x;
    if (e < E) {
        atomicAdd(&g_outdeg[src[e]], 1);
        atomicAdd(&g_indeg[dst[e]], 1);
    }
}

// 3) exclusive prefix scan of indeg -> rowstart (single block, N <= 16384)
__global__ void k_scan(int N, int E) {
    __shared__ int ssum[1024];
    int t = threadIdx.x;
    int items = (N + 1023) >> 10;
    int base = t * items;
    int s = 0;
    for (int i = 0; i < items; i++) {
        int j = base + i;
        if (j < N) s += g_indeg[j];
    }
    ssum[t] = s;
    __syncthreads();
    for (int off = 1; off < 1024; off <<= 1) {
        int v = (t >= off) ? ssum[t - off] : 0;
        __syncthreads();
        ssum[t] += v;
        __syncthreads();
    }
    int run = (t == 0) ? 0 : ssum[t - 1];
    for (int i = 0; i < items; i++) {
        int j = base + i;
        if (j < N) { g_rowstart[j] = run; run += g_indeg[j]; }
    }
    if (t == 1023) g_rowstart[N] = E;
}

// 4) scatter edges into CSR-by-dst, with per-edge alpha resolved here
__global__ void k_scatter(const int* __restrict__ src, const int* __restrict__ dst,
                          const int* __restrict__ node_id, const float* __restrict__ alpha,
                          int E, int gene_num) {
    int e = blockIdx.x * blockDim.x + threadIdx.x;
    if (e >= E) return;
    int s = src[e], d = dst[e];
    int sid = node_id[s], did = node_id[d];
    int idx = gene_num + 1;
    if (sid >= 0 && did < 0)       idx = sid;
    else if (did >= 0 && sid < 0)  idx = did;
    else if (sid >= 0 && did >= 0) idx = gene_num;
    float av = alpha[idx];
    int pos = atomicAdd(&g_cursor[d], 1);
    int slot = g_rowstart[d] + pos;
    g_esrc[slot] = s;
    g_ealpha[slot] = av;
}

// 5) h = diag(rsqrt(max(outdeg,1))) * X * W   (M=N, K=IN_FEATS, cols=64)
__global__ __launch_bounds__(256) void k_linear(const float* __restrict__ feat,
                                                const float* __restrict__ W,
                                                int N, int K) {
    __shared__ float As[32 * 64];  // [k][r]
    __shared__ float Ws[32 * 64];  // [k][c]
    int tid = threadIdx.x;
    int row0 = blockIdx.x * 64;
    int tx = tid & 15, ty = tid >> 4;
    float acc[4][4] = {};
    int lr = tid >> 2;
    int lseg = tid & 3;

    for (int kk = 0; kk < K; kk += 32) {
        const float* fp = feat + (size_t)(row0 + lr) * K + kk + lseg * 8;
        float4 f0 = *(const float4*)fp;
        float4 f1 = *(const float4*)(fp + 4);
        int kb = lseg * 8;
        As[(kb + 0) * 64 + lr] = f0.x; As[(kb + 1) * 64 + lr] = f0.y;
        As[(kb + 2) * 64 + lr] = f0.z; As[(kb + 3) * 64 + lr] = f0.w;
        As[(kb + 4) * 64 + lr] = f1.x; As[(kb + 5) * 64 + lr] = f1.y;
        As[(kb + 6) * 64 + lr] = f1.z; As[(kb + 7) * 64 + lr] = f1.w;
        const float4* wp = (const float4*)(W + (size_t)kk * 64);
        ((float4*)Ws)[tid * 2]     = wp[tid * 2];
        ((float4*)Ws)[tid * 2 + 1] = wp[tid * 2 + 1];
        __syncthreads();
        #pragma unroll
        for (int k = 0; k < 32; k++) {
            float4 a = *(const float4*)&As[k * 64 + ty * 4];
            float4 b = *(const float4*)&Ws[k * 64 + tx * 4];
            float ar[4] = {a.x, a.y, a.z, a.w};
            float br[4] = {b.x, b.y, b.z, b.w};
            #pragma unroll
            for (int u = 0; u < 4; u++)
                #pragma unroll
                for (int v = 0; v < 4; v++)
                    acc[u][v] += ar[u] * br[v];
        }
        __syncthreads();
    }
    #pragma unroll
    for (int u = 0; u < 4; u++) {
        int row = row0 + ty * 4 + u;
        float dv = (float)g_outdeg[row];
        if (dv < 1.0f) dv = 1.0f;
        float rs = rsqrtf(dv);
        float* hp = g_h + (size_t)row * NHID + tx * 4;
        hp[0] = acc[u][0] * rs;
        hp[1] = acc[u][1] * rs;
        hp[2] = acc[u][2] * rs;
        hp[3] = acc[u][3] * rs;
    }
}

// 6) aggregate + fused bf16 hi/lo split for the tensor-core GEMM
__global__ void k_aggregate(const float* __restrict__ bias, float* __restrict__ rst, int N) {
    int wid = (blockIdx.x * blockDim.x + threadIdx.x) >> 5;
    int lane = threadIdx.x & 31;
    if (wid >= N) return;
    int start = g_rowstart[wid];
    int end = g_rowstart[wid + 1];
    float a0 = 0.0f, a1 = 0.0f;
    #pragma unroll 4
    for (int p = start; p < end; p++) {
        int s = g_esrc[p];
        float av = g_ealpha[p];
        const float* hp = g_h + (size_t)s * NHID;
        a0 += av * hp[lane];
        a1 += av * hp[lane + 32];
    }
    float dv = (float)(end - start);
    if (dv < 1.0f) dv = 1.0f;
    float rs = rsqrtf(dv);
    float v0 = a0 * rs + bias[lane];
    float v1 = a1 * rs + bias[lane + 32];
    size_t base = (size_t)wid * NHID;
    rst[base + lane]      = v0;
    rst[base + lane + 32] = v1;
    __nv_bfloat16 h0 = __float2bfloat16(v0);
    __nv_bfloat16 h1 = __float2bfloat16(v1);
    g_hi[base + lane]      = h0;
    g_hi[base + lane + 32] = h1;
    g_lo[base + lane]      = __float2bfloat16(v0 - __bfloat162float(h0));
    g_lo[base + lane + 32] = __float2bfloat16(v1 - __bfloat162float(h1));
}

// ---------------------------------------------------------------------------
// 7) adj = rst * rst^T via mma.sync (HMMA) split-bf16 3-pass:
//    D = hiA*hiB^T + hiA*loB^T + loA*hiB^T  (fp32 register accumulators)
//    Symmetry: only bj <= bi tiles compute; both orientations written through
//    a stride-33 smem stage (conflict-free STS / row-read / column-read).
//
// SMEM (dynamic 64 KB): hiA, loA, hiB, loB tiles of [128][64] bf16, SW128
// swizzled (128 B rows). Epilogue Cs[128][33] fp32 reuses offset 0.
#define OFF_HA 0u
#define OFF_LA 16384u
#define OFF_HB 32768u
#define OFF_LB 49152u
#define GM_SMEM 65536u

__global__ __launch_bounds__(256) void k_gemm_mma(float* __restrict__ C, int N) {
    int bi = blockIdx.y, bj = blockIdx.x;
    if (bj > bi) return;
    extern __shared__ char smc[];
    uint32_t sb = smem_u32(smc);
    int tid = threadIdx.x;
    int lane = tid & 31;
    int wid = tid >> 5;
    int warp_m = wid >> 2;        // 0..1 -> 64-row half
    int warp_n = wid & 3;         // 0..3 -> 32-col quarter

    // ---- load operand tiles (row-major 128x64 bf16 = 128 B/row, SW128) ----
    {
        const uint4* hA = (const uint4*)(g_hi + (size_t)bi * 128 * NHID);
        const uint4* lA = (const uint4*)(g_lo + (size_t)bi * 128 * NHID);
        #pragma unroll
        for (int it = 0; it < 4; it++) {
            int idx = it * 256 + tid;          // uint4 index, 1024 total
            int row = idx >> 3, seg = idx & 7;
            uint32_t so = SW128((uint32_t)(row * 128 + seg * 16));
            *(uint4*)(smc + OFF_HA + so) = hA[idx];
            *(uint4*)(smc + OFF_LA + so) = lA[idx];
        }
        if (bj != bi) {
            const uint4* hB = (const uint4*)(g_hi + (size_t)bj * 128 * NHID);
            const uint4* lB = (const uint4*)(g_lo + (size_t)bj * 128 * NHID);
            #pragma unroll
            for (int it = 0; it < 4; it++) {
                int idx = it * 256 + tid;
                int row = idx >> 3, seg = idx & 7;
                uint32_t so = SW128((uint32_t)(row * 128 + seg * 16));
                *(uint4*)(smc + OFF_HB + so) = hB[idx];
                *(uint4*)(smc + OFF_LB + so) = lB[idx];
            }
        }
    }
    __syncthreads();

    // ---- accumulators: warp region 64x32 = 4x4 tiles of m16n8, 4 f32 each ----
    float acc[4][4][4];
    #pragma unroll
    for (int mt = 0; mt < 4; mt++)
        #pragma unroll
        for (int nt = 0; nt < 4; nt++)
            #pragma unroll
            for (int q = 0; q < 4; q++)
                acc[mt][nt][q] = 0.0f;

    // fragment address lane components (constant across passes/ksteps)
    int a_row = warp_m * 64 + (lane & 15);        // + mt*16
    int a_khalf = lane >> 4;                      // 0/1 -> k seg within k16
    int b_row = warp_n * 32 + ((lane >> 4) << 3) + (lane & 7);  // + pair*16
    int b_khalf = (lane >> 3) & 1;

    #pragma unroll
    for (int pass = 0; pass < 3; pass++) {
        uint32_t Abase = sb + ((pass == 2) ? OFF_LA : OFF_HA);
        uint32_t Bbase;
        if (bi == bj) Bbase = sb + ((pass == 1) ? OFF_LA : OFF_HA);
        else          Bbase = sb + ((pass == 1) ? OFF_LB : OFF_HB);

        #pragma unroll
        for (int ks = 0; ks < 4; ks++) {
            uint32_t a[4][4];
            #pragma unroll
            for (int mt = 0; mt < 4; mt++) {
                uint32_t o = (uint32_t)((a_row + mt * 16) * 128 + (ks * 2 + a_khalf) * 16);
                ldm_x4(a[mt][0], a[mt][1], a[mt][2], a[mt][3], Abase + SW128(o));
            }
            uint32_t b[4][2];
            #pragma unroll
            for (int p = 0; p < 2; p++) {   // n-tile pair p covers tiles 2p, 2p+1
                uint32_t o = (uint32_t)((b_row + p * 16) * 128 + (ks * 2 + b_khalf) * 16);
                uint32_t r0, r1, r2, r3;
                ldm_x4(r0, r1, r2, r3, Bbase + SW128(o));
                b[2 * p][0] = r0; b[2 * p][1] = r1;
                b[2 * p + 1][0] = r2; b[2 * p + 1][1] = r3;
            }
            #pragma unroll
            for (int mt = 0; mt < 4; mt++)
                #pragma unroll
                for (int nt = 0; nt < 4; nt++)
                    mma_16816(acc[mt][nt], a[mt], b[nt]);
        }
    }
    __syncthreads();   // all warps done reading operand smem before Cs reuse

    // ---- epilogue: 4 chunks of 32 cols; Cs[128][33] reuses operand smem ----
    float* Cs = (float*)smc;
    int qrow = lane >> 2;           // 0..7
    int qcol = (lane & 3) * 2;      // 0,2,4,6
    for (int c = 0; c < 4; c++) {
        if (warp_n == c) {
            #pragma unroll
            for (int mt = 0; mt < 4; mt++) {
                int r0 = warp_m * 64 + mt * 16 + qrow;
                #pragma unroll
                for (int nt = 0; nt < 4; nt++) {
                    int col = nt * 8 + qcol;
                    Cs[r0 * 33 + col]           = acc[mt][nt][0];
                    Cs[r0 * 33 + col + 1]       = acc[mt][nt][1];
                    Cs[(r0 + 8) * 33 + col]     = acc[mt][nt][2];
                    Cs[(r0 + 8) * 33 + col + 1] = acc[mt][nt][3];
                }
            }
        }
        __syncthreads();
        // normal orientation: C[bi*128+r][bj*128 + c*32 + cc]
        #pragma unroll 4
        for (int it = 0; it < 16; it++) {
            int idx = it * 256 + tid;
            int r = idx >> 5, cc = idx & 31;
            C[(size_t)(bi * 128 + r) * N + bj * 128 + c * 32 + cc] = Cs[r * 33 + cc];
        }
        if (bj < bi) {
            // mirrored: C[bj*128 + c*32 + p][bi*128 + q] = Cs[q][p]
            #pragma unroll 4
            for (int it = 0; it < 16; it++) {
                int idx = it * 256 + tid;
                int p = idx >> 7, q = idx & 127;
                C[(size_t)(bj * 128 + c * 32 + p) * N + bi * 128 + q] = Cs[q * 33 + p];
            }
        }
        __syncthreads();
    }
}

// ---------------------------------------------------------------------------
extern "C" void kernel_launch(void* const* d_in, const int* in_sizes, int n_in,
                              void* d_out, int out_size) {
    const float* feat    = (const float*)d_in[0];   // [N, IN_FEATS]
    const float* W       = (const float*)d_in[1];   // [IN_FEATS, 64]
    const float* bias    = (const float*)d_in[2];   // [64]
    const float* alpha   = (const float*)d_in[3];   // [gene_num+2]
    const int*   src     = (const int*)d_in[4];     // [E]
    const int*   dst     = (const int*)d_in[5];     // [E]
    const int*   node_id = (const int*)d_in[6];     // [N]

    int N = in_sizes[6];
    int E = in_sizes[4];
    int K = in_sizes[0] / N;           // IN_FEATS
    int gene_num = in_sizes[3] - 2;

    float* out = (float*)d_out;                  // adj [N,N] then rst [N,64]
    float* rst = out + (size_t)N * N;

    k_zero<<<(N + 255) / 256, 256>>>(N);
    k_degrees<<<(E + 255) / 256, 256>>>(src, dst, E);
    k_scan<<<1, 1024>>>(N, E);
    k_scatter<<<(E + 255) / 256, 256>>>(src, dst, node_id, alpha, E, gene_num);
    k_linear<<<N / 64, 256>>>(feat, W, N, K);
    k_aggregate<<<(N * 32 + 255) / 256, 256>>>(bias, rst, N);

    cudaFuncSetAttribute(k_gemm_mma, cudaFuncAttributeMaxDynamicSharedMemorySize, GM_SMEM);
    dim3 grid(N / 128, N / 128);
    k_gemm_mma<<<grid, 256, GM_SMEM>>>(out, N);
}